// round 1
// baseline (speedup 1.0000x reference)
#include <cuda_runtime.h>

// ---------------------------------------------------------------------------
// ReprogrammingLayer_MLA — fp32 SIMT baseline
//   q  = LN(te @ q_a_w^T) @ q_b_w^T                      (4096 x 1024)
//   kv = LN(se @ kv_a_w^T) @ kv_b_w^T                    (1000 x 2048)
//   attn: per (b,h): softmax(Q K^T / 8) V  (flash-style) (4096 x 1024)
//   out = attn @ out_w^T + out_b                         (4096 x 4096)
// ---------------------------------------------------------------------------

#define LN_EPS 1e-5f

// scratch (device globals; no allocation allowed)
__device__ float g_qa  [4096u * 512u];   // 8 MB
__device__ float g_q   [4096u * 1024u];  // 16 MB
__device__ float g_ckv [1000u * 512u];   // 2 MB
__device__ float g_kv  [1000u * 2048u];  // 8 MB
__device__ float g_attn[4096u * 1024u];  // 16 MB

// ---------------------------------------------------------------------------
// Tiled GEMM: C[M,N] = A[M,K] @ B[N,K]^T (+ bias). Row-major, K contiguous.
// BM=BN=64, BK=16, 256 threads, 4x4 micro-tile per thread.
// K must be a multiple of 16, N a multiple of 64; M arbitrary (guarded).
// ---------------------------------------------------------------------------
template<bool ADD_BIAS>
__global__ __launch_bounds__(256) void gemm_tn(
    const float* __restrict__ A, const float* __restrict__ B,
    const float* __restrict__ bias, float* __restrict__ C,
    int M, int N, int K)
{
    __shared__ float As[16][68];   // [k][m], padded
    __shared__ float Bs[16][68];   // [k][n], padded

    const int bm = blockIdx.y * 64;
    const int bn = blockIdx.x * 64;
    const int tid = threadIdx.x;
    const int tx = tid & 15;
    const int ty = tid >> 4;
    const int lr = tid >> 2;          // 0..63 row within tile
    const int lc = (tid & 3) << 2;    // 0,4,8,12 k-offset

    float acc[4][4] = {};

    const float* Aptr = A + (size_t)(bm + lr) * K + lc;
    const float* Bptr = B + (size_t)(bn + lr) * K + lc;
    const bool arow_ok = (bm + lr) < M;

    for (int k0 = 0; k0 < K; k0 += 16) {
        float4 av = arow_ok ? *(const float4*)(Aptr + k0) : make_float4(0.f,0.f,0.f,0.f);
        float4 bv = *(const float4*)(Bptr + k0);
        As[lc+0][lr] = av.x; As[lc+1][lr] = av.y; As[lc+2][lr] = av.z; As[lc+3][lr] = av.w;
        Bs[lc+0][lr] = bv.x; Bs[lc+1][lr] = bv.y; Bs[lc+2][lr] = bv.z; Bs[lc+3][lr] = bv.w;
        __syncthreads();
        #pragma unroll
        for (int kk = 0; kk < 16; kk++) {
            float4 a4 = *(const float4*)&As[kk][ty << 2];
            float4 b4 = *(const float4*)&Bs[kk][tx << 2];
            float af[4] = {a4.x, a4.y, a4.z, a4.w};
            float bf[4] = {b4.x, b4.y, b4.z, b4.w};
            #pragma unroll
            for (int i = 0; i < 4; i++)
                #pragma unroll
                for (int j = 0; j < 4; j++)
                    acc[i][j] = fmaf(af[i], bf[j], acc[i][j]);
        }
        __syncthreads();
    }

    #pragma unroll
    for (int i = 0; i < 4; i++) {
        int row = bm + (ty << 2) + i;
        if (row >= M) continue;
        #pragma unroll
        for (int j = 0; j < 4; j++) {
            int col = bn + (tx << 2) + j;
            float v = acc[i][j];
            if (ADD_BIAS) v += bias[col];
            C[(size_t)row * N + col] = v;
        }
    }
}

// ---------------------------------------------------------------------------
// LayerNorm over 512 columns, one block per row, in place.
// ---------------------------------------------------------------------------
__global__ __launch_bounds__(256) void ln_kernel(
    float* __restrict__ x, const float* __restrict__ g,
    const float* __restrict__ b)
{
    const int C = 512;
    float* row = x + (size_t)blockIdx.x * C;
    const int t = threadIdx.x;

    float v0 = row[t];
    float v1 = row[t + 256];
    float s  = v0 + v1;
    float sq = v0 * v0 + v1 * v1;

    #pragma unroll
    for (int o = 16; o > 0; o >>= 1) {
        s  += __shfl_xor_sync(0xffffffffu, s,  o);
        sq += __shfl_xor_sync(0xffffffffu, sq, o);
    }
    __shared__ float redS[8], redQ[8];
    const int warp = t >> 5, lane = t & 31;
    if (lane == 0) { redS[warp] = s; redQ[warp] = sq; }
    __syncthreads();
    float S = 0.f, Q = 0.f;
    #pragma unroll
    for (int w = 0; w < 8; w++) { S += redS[w]; Q += redQ[w]; }

    const float mu  = S * (1.0f / C);
    const float var = Q * (1.0f / C) - mu * mu;
    const float r   = rsqrtf(var + LN_EPS);

    row[t]       = (v0 - mu) * r * g[t]       + b[t];
    row[t + 256] = (v1 - mu) * r * g[t + 256] + b[t + 256];
}

// ---------------------------------------------------------------------------
// Flash attention per (qblock=64 queries, head, batch).
// Q: g_q[4096][1024] (row = b*1024+l, col = h*64+d)
// KV: g_kv[1000][2048] (col = h*128 + d for K, h*128+64+d for V)
// 48 KB static smem: Qst (Q^T), KV (K^T then V), Ps (probabilities).
// ---------------------------------------------------------------------------
__global__ __launch_bounds__(256) void attn_kernel(
    const float* __restrict__ q, const float* __restrict__ kv,
    float* __restrict__ out, int S)
{
    __shared__ float Qst[64][64];  // [d][i]
    __shared__ float KVs[64][64];  // K phase: [d][j] ; V phase: [j][d]
    __shared__ float Ps [64][64];  // [i][j]

    const int qb = blockIdx.x;   // 0..15
    const int h  = blockIdx.y;   // 0..15
    const int b  = blockIdx.z;   // 0..3
    const int tid = threadIdx.x;
    const int tx = tid & 15;
    const int ty = tid >> 4;
    const float scale = 0.125f;  // 1/sqrt(64)

    const float* qbase = q + ((size_t)(b * 1024 + qb * 64)) * 1024 + (size_t)h * 64;
    for (int idx = tid; idx < 4096; idx += 256) {
        int i = idx >> 6, d = idx & 63;
        Qst[d][i] = qbase[(size_t)i * 1024 + d] * scale;
    }

    float m[4], l[4], acc[4][4];
    #pragma unroll
    for (int i = 0; i < 4; i++) {
        m[i] = -1e30f; l[i] = 0.f;
        #pragma unroll
        for (int j = 0; j < 4; j++) acc[i][j] = 0.f;
    }

    for (int s0 = 0; s0 < S; s0 += 64) {
        __syncthreads();  // prev-iteration readers of KVs/Ps done
        // --- load K chunk transposed: KVs[d][j] ---
        for (int idx = tid; idx < 4096; idx += 256) {
            int j = idx >> 6, d = idx & 63;
            int s = s0 + j;
            KVs[d][j] = (s < S) ? kv[(size_t)s * 2048 + h * 128 + d] : 0.f;
        }
        __syncthreads();

        // --- scores = (Q*scale) @ K^T ---
        float sc[4][4];
        #pragma unroll
        for (int i = 0; i < 4; i++)
            #pragma unroll
            for (int j = 0; j < 4; j++) sc[i][j] = 0.f;
        #pragma unroll 8
        for (int d = 0; d < 64; d++) {
            float4 a4 = *(const float4*)&Qst[d][ty << 2];
            float4 b4 = *(const float4*)&KVs[d][tx << 2];
            float af[4] = {a4.x, a4.y, a4.z, a4.w};
            float bf[4] = {b4.x, b4.y, b4.z, b4.w};
            #pragma unroll
            for (int i = 0; i < 4; i++)
                #pragma unroll
                for (int j = 0; j < 4; j++)
                    sc[i][j] = fmaf(af[i], bf[j], sc[i][j]);
        }

        // --- mask tail of last chunk ---
        if (s0 + 64 > S) {
            #pragma unroll
            for (int j = 0; j < 4; j++)
                if (s0 + (tx << 2) + j >= S) {
                    #pragma unroll
                    for (int i = 0; i < 4; i++) sc[i][j] = -1e30f;
                }
        }

        // --- online softmax update (rows shared across 16-lane groups) ---
        #pragma unroll
        for (int i = 0; i < 4; i++) {
            float v = fmaxf(fmaxf(sc[i][0], sc[i][1]), fmaxf(sc[i][2], sc[i][3]));
            #pragma unroll
            for (int o = 8; o > 0; o >>= 1)
                v = fmaxf(v, __shfl_xor_sync(0xffffffffu, v, o, 16));
            float mnew = fmaxf(m[i], v);
            float sum = 0.f;
            #pragma unroll
            for (int j = 0; j < 4; j++) {
                float p = __expf(sc[i][j] - mnew);
                sc[i][j] = p;
                sum += p;
            }
            #pragma unroll
            for (int o = 8; o > 0; o >>= 1)
                sum += __shfl_xor_sync(0xffffffffu, sum, o, 16);
            float corr = __expf(m[i] - mnew);
            l[i] = l[i] * corr + sum;
            m[i] = mnew;
            #pragma unroll
            for (int j = 0; j < 4; j++) acc[i][j] *= corr;
        }

        __syncthreads();  // everyone done reading KVs (K)
        // --- store P, load V chunk into KVs[j][d] ---
        #pragma unroll
        for (int i = 0; i < 4; i++)
            *(float4*)&Ps[(ty << 2) + i][tx << 2] =
                make_float4(sc[i][0], sc[i][1], sc[i][2], sc[i][3]);
        for (int idx = tid; idx < 4096; idx += 256) {
            int j = idx >> 6, d = idx & 63;
            int s = s0 + j;
            KVs[j][d] = (s < S) ? kv[(size_t)s * 2048 + h * 128 + 64 + d] : 0.f;
        }
        __syncthreads();

        // --- acc += P @ V ---
        #pragma unroll 8
        for (int s = 0; s < 64; s++) {
            float af[4];
            #pragma unroll
            for (int i = 0; i < 4; i++) af[i] = Ps[(ty << 2) + i][s];
            float4 b4 = *(const float4*)&KVs[s][tx << 2];
            float bf[4] = {b4.x, b4.y, b4.z, b4.w};
            #pragma unroll
            for (int i = 0; i < 4; i++)
                #pragma unroll
                for (int j = 0; j < 4; j++)
                    acc[i][j] = fmaf(af[i], bf[j], acc[i][j]);
        }
    }

    // --- epilogue: normalize and write ---
    float* ob = out + ((size_t)(b * 1024 + qb * 64)) * 1024 + (size_t)h * 64;
    #pragma unroll
    for (int i = 0; i < 4; i++) {
        float inv = 1.0f / l[i];
        #pragma unroll
        for (int j = 0; j < 4; j++)
            ob[(size_t)((ty << 2) + i) * 1024 + (tx << 2) + j] = acc[i][j] * inv;
    }
}

// ---------------------------------------------------------------------------
extern "C" void kernel_launch(void* const* d_in, const int* in_sizes, int n_in,
                              void* d_out, int out_size)
{
    (void)in_sizes; (void)n_in; (void)out_size;
    const float* te      = (const float*)d_in[0];   // (4,1024,1024)
    const float* se      = (const float*)d_in[1];   // (1000,4096)
    // d_in[2] value_embedding: unused by reference
    const float* q_a_w   = (const float*)d_in[3];   // (512,1024)
    const float* q_ln_g  = (const float*)d_in[4];
    const float* q_ln_b  = (const float*)d_in[5];
    const float* q_b_w   = (const float*)d_in[6];   // (1024,512)
    const float* kv_a_w  = (const float*)d_in[7];   // (512,4096)
    const float* kv_ln_g = (const float*)d_in[8];
    const float* kv_ln_b = (const float*)d_in[9];
    const float* kv_b_w  = (const float*)d_in[10];  // (2048,512)
    const float* out_w   = (const float*)d_in[11];  // (4096,1024)
    const float* out_b   = (const float*)d_in[12];  // (4096,)
    float* out = (float*)d_out;                     // (4,1024,4096)

    float *qa, *qbuf, *ckv, *kvb, *attn;
    cudaGetSymbolAddress((void**)&qa,   g_qa);
    cudaGetSymbolAddress((void**)&qbuf, g_q);
    cudaGetSymbolAddress((void**)&ckv,  g_ckv);
    cudaGetSymbolAddress((void**)&kvb,  g_kv);
    cudaGetSymbolAddress((void**)&attn, g_attn);

    // q path
    gemm_tn<false><<<dim3(8, 64), 256>>>(te, q_a_w, nullptr, qa, 4096, 512, 1024);
    ln_kernel<<<4096, 256>>>(qa, q_ln_g, q_ln_b);
    gemm_tn<false><<<dim3(16, 64), 256>>>(qa, q_b_w, nullptr, qbuf, 4096, 1024, 512);

    // kv path
    gemm_tn<false><<<dim3(8, 16), 256>>>(se, kv_a_w, nullptr, ckv, 1000, 512, 4096);
    ln_kernel<<<1000, 256>>>(ckv, kv_ln_g, kv_ln_b);
    gemm_tn<false><<<dim3(32, 16), 256>>>(ckv, kv_b_w, nullptr, kvb, 1000, 2048, 512);

    // attention
    attn_kernel<<<dim3(16, 16, 4), 256>>>(qbuf, kvb, attn, 1000);

    // output projection + bias
    gemm_tn<true><<<dim3(64, 64), 256>>>(attn, out_w, out_b, out, 4096, 4096, 1024);
}

// round 7
// speedup vs baseline: 1.6767x; 1.6767x over previous
#include <cuda_runtime.h>
#include <cstdint>

// ===========================================================================
// ReprogrammingLayer_MLA — round 7
//   GEMMs: mma.sync.m16n8k16 bf16 (HMMA tensor cores), hi/lo 3-term split
//          for fp32-grade accuracy. Standard PTX (sm_80+): no tcgen05, no
//          TMEM, no mbarrier — eliminates the R3-R6 failure surface.
//   LayerNorm + flash attention: fp32 SIMT (proven round 1)
// ===========================================================================

#define LN_EPS 1e-5f

// scratch (device globals; no allocation allowed)
__device__ float g_qa  [4096u * 512u];
__device__ float g_q   [4096u * 1024u];
__device__ float g_ckv [1000u * 512u];
__device__ float g_kv  [1000u * 2048u];
__device__ float g_attn[4096u * 1024u];

// ---------------------------------------------------------------------------
// helpers
// ---------------------------------------------------------------------------
__device__ __forceinline__ uint32_t smem_u32(const void* p) {
    uint32_t a;
    asm("{ .reg .u64 t; cvta.to.shared.u64 t, %1; cvt.u32.u64 %0, t; }"
        : "=r"(a) : "l"(p));
    return a;
}

__device__ __forceinline__ uint32_t pack_bf16(float lo, float hi) {
    // [15:0] = bf16(lo), [31:16] = bf16(hi)
    uint32_t r;
    asm("cvt.rn.bf16x2.f32 %0, %1, %2;" : "=r"(r) : "f"(hi), "f"(lo));
    return r;
}

__device__ __forceinline__ void ldsm4(uint32_t* r, uint32_t addr) {
    asm volatile("ldmatrix.sync.aligned.m8n8.x4.shared.b16 {%0,%1,%2,%3}, [%4];"
                 : "=r"(r[0]), "=r"(r[1]), "=r"(r[2]), "=r"(r[3]) : "r"(addr));
}

__device__ __forceinline__ void mma16816(float* c, const uint32_t* a,
                                         const uint32_t* b) {
    asm volatile(
        "mma.sync.aligned.m16n8k16.row.col.f32.bf16.bf16.f32 "
        "{%0,%1,%2,%3}, {%4,%5,%6,%7}, {%8,%9}, {%0,%1,%2,%3};"
        : "+f"(c[0]), "+f"(c[1]), "+f"(c[2]), "+f"(c[3])
        : "r"(a[0]), "r"(a[1]), "r"(a[2]), "r"(a[3]), "r"(b[0]), "r"(b[1]));
}

// ---------------------------------------------------------------------------
// bf16x3 mma.sync GEMM: C[M,N] = A[M,K] @ B[N,K]^T (+bias), fp32 in gmem.
// BM=BN=128, BK=32. 256 threads = 8 warps (2 M x 4 N); warp = 64x32 output.
// SMEM: 4 bf16 tiles [128 rows x (32+8pad)] : Ah, Al, Bh, Bl = 40 KB static.
// Row stride 80B -> ldmatrix conflict-free (row*20 mod 32 banks distinct).
// ---------------------------------------------------------------------------
#define ROWU 20                 // uint32 per smem row (40 bf16)
#define TILE_U32 (128 * ROWU)   // 2560 u32 = 10240 B per tile

template<bool ADD_BIAS>
__global__ __launch_bounds__(256) void gemm_mma(
    const float* __restrict__ A, const float* __restrict__ B,
    const float* __restrict__ bias, float* __restrict__ C,
    int M, int N, int K)
{
    __shared__ uint32_t sm[4 * TILE_U32];   // Ah | Al | Bh | Bl

    const int tid  = threadIdx.x;
    const int wid  = tid >> 5;
    const int lane = tid & 31;
    const int warpM = wid >> 2;     // 0..1
    const int warpN = wid & 3;      // 0..3
    const int bm = blockIdx.y * 128;
    const int bn = blockIdx.x * 128;
    const int nchunks = K >> 5;

    const uint32_t smb = smem_u32(sm);

    float acc[16][4];
    #pragma unroll
    for (int i = 0; i < 16; i++)
        #pragma unroll
        for (int j = 0; j < 4; j++) acc[i][j] = 0.f;

    // per-thread load indices: 1024 float4 per tile, 4 per thread
    const int lrow = tid >> 1;            // unused pattern below uses idx math
    (void)lrow;

    float4 ar[4], br[4];

    // ---- prologue: load + stage chunk 0 ----
    {
        #pragma unroll
        for (int i = 0; i < 4; i++) {
            int idx = i * 256 + tid;
            int row = idx >> 3, q = idx & 7;
            int gr = bm + row; if (gr >= M) gr = M - 1;
            ar[i] = *(const float4*)(A + (size_t)gr * K + q * 4);
            br[i] = *(const float4*)(B + (size_t)(bn + row) * K + q * 4);
        }
        #pragma unroll
        for (int i = 0; i < 4; i++) {
            int idx = i * 256 + tid;
            int row = idx >> 3, q = idx & 7;
            // A hi/lo
            float4 v = ar[i];
            uint32_t h01 = pack_bf16(v.x, v.y), h23 = pack_bf16(v.z, v.w);
            float hx = __uint_as_float(h01 << 16);
            float hy = __uint_as_float(h01 & 0xffff0000u);
            float hz = __uint_as_float(h23 << 16);
            float hw = __uint_as_float(h23 & 0xffff0000u);
            sm[row * ROWU + q * 2]     = h01;
            sm[row * ROWU + q * 2 + 1] = h23;
            sm[TILE_U32 + row * ROWU + q * 2]     = pack_bf16(v.x - hx, v.y - hy);
            sm[TILE_U32 + row * ROWU + q * 2 + 1] = pack_bf16(v.z - hz, v.w - hw);
            // B hi/lo
            v = br[i];
            h01 = pack_bf16(v.x, v.y); h23 = pack_bf16(v.z, v.w);
            hx = __uint_as_float(h01 << 16);
            hy = __uint_as_float(h01 & 0xffff0000u);
            hz = __uint_as_float(h23 << 16);
            hw = __uint_as_float(h23 & 0xffff0000u);
            sm[2 * TILE_U32 + row * ROWU + q * 2]     = h01;
            sm[2 * TILE_U32 + row * ROWU + q * 2 + 1] = h23;
            sm[3 * TILE_U32 + row * ROWU + q * 2]     = pack_bf16(v.x - hx, v.y - hy);
            sm[3 * TILE_U32 + row * ROWU + q * 2 + 1] = pack_bf16(v.z - hz, v.w - hw);
        }
    }
    __syncthreads();

    // fragment address components (bytes)
    const uint32_t aoff = (uint32_t)((lane & 15) * 80 + (lane >> 4) * 16);
    const uint32_t boff = (uint32_t)((((lane >> 4) & 1) * 8 + (lane & 7)) * 80 +
                                     ((lane >> 3) & 1) * 16);
    const uint32_t aBase = smb + (uint32_t)(warpM * 64) * 80 + aoff;
    const uint32_t bBase = smb + 2u * 10240u + (uint32_t)(warpN * 32) * 80 + boff;

    for (int c = 0; c < nchunks; c++) {
        // prefetch next chunk to regs (overlaps MMA below)
        const bool more = (c + 1 < nchunks);
        if (more) {
            const int k0 = (c + 1) * 32;
            #pragma unroll
            for (int i = 0; i < 4; i++) {
                int idx = i * 256 + tid;
                int row = idx >> 3, q = idx & 7;
                int gr = bm + row; if (gr >= M) gr = M - 1;
                ar[i] = *(const float4*)(A + (size_t)gr * K + k0 + q * 4);
                br[i] = *(const float4*)(B + (size_t)(bn + row) * K + k0 + q * 4);
            }
        }

        // ---- compute on staged chunk ----
        #pragma unroll
        for (int ks = 0; ks < 2; ks++) {
            const uint32_t kb = (uint32_t)(ks * 32);
            uint32_t ah[4][4], al[4][4], bh[2][4], bl[2][4];
            #pragma unroll
            for (int mt = 0; mt < 4; mt++)
                ldsm4(ah[mt], aBase + (uint32_t)(mt * 16) * 80 + kb);
            #pragma unroll
            for (int p = 0; p < 2; p++)
                ldsm4(bh[p], bBase + (uint32_t)(p * 16) * 80 + kb);
            #pragma unroll
            for (int mt = 0; mt < 4; mt++)
                #pragma unroll
                for (int nt = 0; nt < 4; nt++)
                    mma16816(acc[mt * 4 + nt], ah[mt], &bh[nt >> 1][(nt & 1) * 2]);
            #pragma unroll
            for (int p = 0; p < 2; p++)
                ldsm4(bl[p], bBase + 10240u + (uint32_t)(p * 16) * 80 + kb);
            #pragma unroll
            for (int mt = 0; mt < 4; mt++)
                #pragma unroll
                for (int nt = 0; nt < 4; nt++)
                    mma16816(acc[mt * 4 + nt], ah[mt], &bl[nt >> 1][(nt & 1) * 2]);
            #pragma unroll
            for (int mt = 0; mt < 4; mt++)
                ldsm4(al[mt], aBase + 10240u + (uint32_t)(mt * 16) * 80 + kb);
            #pragma unroll
            for (int mt = 0; mt < 4; mt++)
                #pragma unroll
                for (int nt = 0; nt < 4; nt++)
                    mma16816(acc[mt * 4 + nt], al[mt], &bh[nt >> 1][(nt & 1) * 2]);
        }
        __syncthreads();

        if (more) {
            #pragma unroll
            for (int i = 0; i < 4; i++) {
                int idx = i * 256 + tid;
                int row = idx >> 3, q = idx & 7;
                float4 v = ar[i];
                uint32_t h01 = pack_bf16(v.x, v.y), h23 = pack_bf16(v.z, v.w);
                float hx = __uint_as_float(h01 << 16);
                float hy = __uint_as_float(h01 & 0xffff0000u);
                float hz = __uint_as_float(h23 << 16);
                float hw = __uint_as_float(h23 & 0xffff0000u);
                sm[row * ROWU + q * 2]     = h01;
                sm[row * ROWU + q * 2 + 1] = h23;
                sm[TILE_U32 + row * ROWU + q * 2]     = pack_bf16(v.x - hx, v.y - hy);
                sm[TILE_U32 + row * ROWU + q * 2 + 1] = pack_bf16(v.z - hz, v.w - hw);
                v = br[i];
                h01 = pack_bf16(v.x, v.y); h23 = pack_bf16(v.z, v.w);
                hx = __uint_as_float(h01 << 16);
                hy = __uint_as_float(h01 & 0xffff0000u);
                hz = __uint_as_float(h23 << 16);
                hw = __uint_as_float(h23 & 0xffff0000u);
                sm[2 * TILE_U32 + row * ROWU + q * 2]     = h01;
                sm[2 * TILE_U32 + row * ROWU + q * 2 + 1] = h23;
                sm[3 * TILE_U32 + row * ROWU + q * 2]     = pack_bf16(v.x - hx, v.y - hy);
                sm[3 * TILE_U32 + row * ROWU + q * 2 + 1] = pack_bf16(v.z - hz, v.w - hw);
            }
            __syncthreads();
        }
    }

    // ---- epilogue: fragment layout -> gmem (guarded rows) ----
    const int gcol0 = bn + warpN * 32;
    #pragma unroll
    for (int mt = 0; mt < 4; mt++) {
        const int gr0 = bm + warpM * 64 + mt * 16 + (lane >> 2);
        #pragma unroll
        for (int nt = 0; nt < 4; nt++) {
            const int gc = gcol0 + nt * 8 + (lane & 3) * 2;
            float b0 = 0.f, b1 = 0.f;
            if (ADD_BIAS) { b0 = bias[gc]; b1 = bias[gc + 1]; }
            const float* cc = acc[mt * 4 + nt];
            if (gr0 < M) {
                C[(size_t)gr0 * N + gc]     = cc[0] + b0;
                C[(size_t)gr0 * N + gc + 1] = cc[1] + b1;
            }
            if (gr0 + 8 < M) {
                C[(size_t)(gr0 + 8) * N + gc]     = cc[2] + b0;
                C[(size_t)(gr0 + 8) * N + gc + 1] = cc[3] + b1;
            }
        }
    }
}

// ---------------------------------------------------------------------------
// LayerNorm over 512 columns, one block per row, in place.
// ---------------------------------------------------------------------------
__global__ __launch_bounds__(256) void ln_kernel(
    float* __restrict__ x, const float* __restrict__ g,
    const float* __restrict__ b)
{
    const int C = 512;
    float* row = x + (size_t)blockIdx.x * C;
    const int t = threadIdx.x;

    float v0 = row[t];
    float v1 = row[t + 256];
    float s  = v0 + v1;
    float sq = v0 * v0 + v1 * v1;

    #pragma unroll
    for (int o = 16; o > 0; o >>= 1) {
        s  += __shfl_xor_sync(0xffffffffu, s,  o);
        sq += __shfl_xor_sync(0xffffffffu, sq, o);
    }
    __shared__ float redS[8], redQ[8];
    const int warp = t >> 5, lane = t & 31;
    if (lane == 0) { redS[warp] = s; redQ[warp] = sq; }
    __syncthreads();
    float S = 0.f, Q = 0.f;
    #pragma unroll
    for (int w = 0; w < 8; w++) { S += redS[w]; Q += redQ[w]; }

    const float mu  = S * (1.0f / C);
    const float var = Q * (1.0f / C) - mu * mu;
    const float r   = rsqrtf(var + LN_EPS);

    row[t]       = (v0 - mu) * r * g[t]       + b[t];
    row[t + 256] = (v1 - mu) * r * g[t + 256] + b[t + 256];
}

// ---------------------------------------------------------------------------
// Flash attention per (qblock=64 queries, head, batch) — fp32 SIMT
// ---------------------------------------------------------------------------
__global__ __launch_bounds__(256) void attn_kernel(
    const float* __restrict__ q, const float* __restrict__ kv,
    float* __restrict__ out, int S)
{
    __shared__ float Qst[64][64];
    __shared__ float KVs[64][64];
    __shared__ float Ps [64][64];

    const int qb = blockIdx.x;
    const int h  = blockIdx.y;
    const int b  = blockIdx.z;
    const int tid = threadIdx.x;
    const int tx = tid & 15;
    const int ty = tid >> 4;
    const float scale = 0.125f;

    const float* qbase = q + ((size_t)(b * 1024 + qb * 64)) * 1024 + (size_t)h * 64;
    for (int idx = tid; idx < 4096; idx += 256) {
        int i = idx >> 6, d = idx & 63;
        Qst[d][i] = qbase[(size_t)i * 1024 + d] * scale;
    }

    float m[4], l[4], acc[4][4];
    #pragma unroll
    for (int i = 0; i < 4; i++) {
        m[i] = -1e30f; l[i] = 0.f;
        #pragma unroll
        for (int j = 0; j < 4; j++) acc[i][j] = 0.f;
    }

    for (int s0 = 0; s0 < S; s0 += 64) {
        __syncthreads();
        for (int idx = tid; idx < 4096; idx += 256) {
            int j = idx >> 6, d = idx & 63;
            int s = s0 + j;
            KVs[d][j] = (s < S) ? kv[(size_t)s * 2048 + h * 128 + d] : 0.f;
        }
        __syncthreads();

        float sc[4][4];
        #pragma unroll
        for (int i = 0; i < 4; i++)
            #pragma unroll
            for (int j = 0; j < 4; j++) sc[i][j] = 0.f;
        #pragma unroll 8
        for (int d = 0; d < 64; d++) {
            float4 a4 = *(const float4*)&Qst[d][ty << 2];
            float4 b4 = *(const float4*)&KVs[d][tx << 2];
            float af[4] = {a4.x, a4.y, a4.z, a4.w};
            float bf[4] = {b4.x, b4.y, b4.z, b4.w};
            #pragma unroll
            for (int i = 0; i < 4; i++)
                #pragma unroll
                for (int j = 0; j < 4; j++)
                    sc[i][j] = fmaf(af[i], bf[j], sc[i][j]);
        }

        if (s0 + 64 > S) {
            #pragma unroll
            for (int j = 0; j < 4; j++)
                if (s0 + (tx << 2) + j >= S) {
                    #pragma unroll
                    for (int i = 0; i < 4; i++) sc[i][j] = -1e30f;
                }
        }

        #pragma unroll
        for (int i = 0; i < 4; i++) {
            float v = fmaxf(fmaxf(sc[i][0], sc[i][1]), fmaxf(sc[i][2], sc[i][3]));
            #pragma unroll
            for (int o = 8; o > 0; o >>= 1)
                v = fmaxf(v, __shfl_xor_sync(0xffffffffu, v, o, 16));
            float mnew = fmaxf(m[i], v);
            float sum = 0.f;
            #pragma unroll
            for (int j = 0; j < 4; j++) {
                float p = __expf(sc[i][j] - mnew);
                sc[i][j] = p;
                sum += p;
            }
            #pragma unroll
            for (int o = 8; o > 0; o >>= 1)
                sum += __shfl_xor_sync(0xffffffffu, sum, o, 16);
            float corr = __expf(m[i] - mnew);
            l[i] = l[i] * corr + sum;
            m[i] = mnew;
            #pragma unroll
            for (int j = 0; j < 4; j++) acc[i][j] *= corr;
        }

        __syncthreads();
        #pragma unroll
        for (int i = 0; i < 4; i++)
            *(float4*)&Ps[(ty << 2) + i][tx << 2] =
                make_float4(sc[i][0], sc[i][1], sc[i][2], sc[i][3]);
        for (int idx = tid; idx < 4096; idx += 256) {
            int j = idx >> 6, d = idx & 63;
            int s = s0 + j;
            KVs[j][d] = (s < S) ? kv[(size_t)s * 2048 + h * 128 + 64 + d] : 0.f;
        }
        __syncthreads();

        #pragma unroll 8
        for (int s = 0; s < 64; s++) {
            float af[4];
            #pragma unroll
            for (int i = 0; i < 4; i++) af[i] = Ps[(ty << 2) + i][s];
            float4 b4 = *(const float4*)&KVs[s][tx << 2];
            float bf[4] = {b4.x, b4.y, b4.z, b4.w};
            #pragma unroll
            for (int i = 0; i < 4; i++)
                #pragma unroll
                for (int j = 0; j < 4; j++)
                    acc[i][j] = fmaf(af[i], bf[j], acc[i][j]);
        }
    }

    float* ob = out + ((size_t)(b * 1024 + qb * 64)) * 1024 + (size_t)h * 64;
    #pragma unroll
    for (int i = 0; i < 4; i++) {
        float inv = 1.0f / l[i];
        #pragma unroll
        for (int j = 0; j < 4; j++)
            ob[(size_t)((ty << 2) + i) * 1024 + (tx << 2) + j] = acc[i][j] * inv;
    }
}

// ---------------------------------------------------------------------------
extern "C" void kernel_launch(void* const* d_in, const int* in_sizes, int n_in,
                              void* d_out, int out_size)
{
    (void)in_sizes; (void)n_in; (void)out_size;
    const float* te      = (const float*)d_in[0];
    const float* se      = (const float*)d_in[1];
    const float* q_a_w   = (const float*)d_in[3];
    const float* q_ln_g  = (const float*)d_in[4];
    const float* q_ln_b  = (const float*)d_in[5];
    const float* q_b_w   = (const float*)d_in[6];
    const float* kv_a_w  = (const float*)d_in[7];
    const float* kv_ln_g = (const float*)d_in[8];
    const float* kv_ln_b = (const float*)d_in[9];
    const float* kv_b_w  = (const float*)d_in[10];
    const float* out_w   = (const float*)d_in[11];
    const float* out_b   = (const float*)d_in[12];
    float* out = (float*)d_out;

    float *qa, *qbuf, *ckv, *kvb, *attn;
    cudaGetSymbolAddress((void**)&qa,   g_qa);
    cudaGetSymbolAddress((void**)&qbuf, g_q);
    cudaGetSymbolAddress((void**)&ckv,  g_ckv);
    cudaGetSymbolAddress((void**)&kvb,  g_kv);
    cudaGetSymbolAddress((void**)&attn, g_attn);

    // q path: (4096x512 K=1024), LN, (4096x1024 K=512)
    gemm_mma<false><<<dim3(4, 32), 256>>>(te, q_a_w, nullptr, qa, 4096, 512, 1024);
    ln_kernel<<<4096, 256>>>(qa, q_ln_g, q_ln_b);
    gemm_mma<false><<<dim3(8, 32), 256>>>(qa, q_b_w, nullptr, qbuf, 4096, 1024, 512);

    // kv path: (1000x512 K=4096), LN, (1000x2048 K=512)
    gemm_mma<false><<<dim3(4, 8), 256>>>(se, kv_a_w, nullptr, ckv, 1000, 512, 4096);
    ln_kernel<<<1000, 256>>>(ckv, kv_ln_g, kv_ln_b);
    gemm_mma<false><<<dim3(16, 8), 256>>>(ckv, kv_b_w, nullptr, kvb, 1000, 2048, 512);

    // attention
    attn_kernel<<<dim3(16, 16, 4), 256>>>(qbuf, kvb, attn, 1000);

    // output projection + bias: (4096x4096 K=1024)
    gemm_mma<true><<<dim3(32, 32), 256>>>(attn, out_w, out_b, out, 4096, 4096, 1024);
}

// round 8
// speedup vs baseline: 3.0258x; 1.8046x over previous
#include <cuda_runtime.h>
#include <cstdint>

// ===========================================================================
// ReprogrammingLayer_MLA — round 8
//   GEMMs: mma.sync m16n8k16 bf16 hi/lo x3 (proven round 7)
//          + split-K for the kv_a GEMM (K=4096, was 32 CTAs -> 128)
//   Attention: flash, mma.sync bf16 hi/lo x3 (Q frags in regs, V via
//          ldmatrix.trans, P reused from S fragments)
//   LayerNorm: fp32 SIMT
// ===========================================================================

#define LN_EPS 1e-5f

// scratch (device globals; no allocation allowed)
__device__ float g_qa  [4096u * 512u];
__device__ float g_q   [4096u * 1024u];
__device__ float g_ckv [1000u * 512u];
__device__ float g_kv  [1000u * 2048u];
__device__ float g_attn[4096u * 1024u];
__device__ float g_part[4u * 1000u * 512u];   // split-K partials (8 MB)

// ---------------------------------------------------------------------------
// helpers
// ---------------------------------------------------------------------------
__device__ __forceinline__ uint32_t smem_u32(const void* p) {
    uint32_t a;
    asm("{ .reg .u64 t; cvta.to.shared.u64 t, %1; cvt.u32.u64 %0, t; }"
        : "=r"(a) : "l"(p));
    return a;
}

__device__ __forceinline__ uint32_t pack_bf16(float lo, float hi) {
    // [15:0] = bf16(lo), [31:16] = bf16(hi)
    uint32_t r;
    asm("cvt.rn.bf16x2.f32 %0, %1, %2;" : "=r"(r) : "f"(hi), "f"(lo));
    return r;
}

__device__ __forceinline__ void ldsm4(uint32_t* r, uint32_t addr) {
    asm volatile("ldmatrix.sync.aligned.m8n8.x4.shared.b16 {%0,%1,%2,%3}, [%4];"
                 : "=r"(r[0]), "=r"(r[1]), "=r"(r[2]), "=r"(r[3]) : "r"(addr));
}
__device__ __forceinline__ void ldsm4t(uint32_t* r, uint32_t addr) {
    asm volatile("ldmatrix.sync.aligned.m8n8.x4.trans.shared.b16 {%0,%1,%2,%3}, [%4];"
                 : "=r"(r[0]), "=r"(r[1]), "=r"(r[2]), "=r"(r[3]) : "r"(addr));
}

__device__ __forceinline__ void mma16816(float* c, const uint32_t* a,
                                         const uint32_t* b) {
    asm volatile(
        "mma.sync.aligned.m16n8k16.row.col.f32.bf16.bf16.f32 "
        "{%0,%1,%2,%3}, {%4,%5,%6,%7}, {%8,%9}, {%0,%1,%2,%3};"
        : "+f"(c[0]), "+f"(c[1]), "+f"(c[2]), "+f"(c[3])
        : "r"(a[0]), "r"(a[1]), "r"(a[2]), "r"(a[3]), "r"(b[0]), "r"(b[1]));
}

// split fp32 pair -> (hi bf16x2, lo bf16x2)
__device__ __forceinline__ void split2(float x, float y, uint32_t& h, uint32_t& l) {
    h = pack_bf16(x, y);
    float hx = __uint_as_float(h << 16);
    float hy = __uint_as_float(h & 0xffff0000u);
    l = pack_bf16(x - hx, y - hy);
}

// ---------------------------------------------------------------------------
// bf16x3 mma.sync GEMM (round 7, + split-K)
// ---------------------------------------------------------------------------
#define ROWU 20
#define TILE_U32 (128 * ROWU)

template<bool ADD_BIAS, bool SPLIT>
__global__ __launch_bounds__(256) void gemm_mma(
    const float* __restrict__ A, const float* __restrict__ B,
    const float* __restrict__ bias, float* __restrict__ C,
    int M, int N, int Kit, int ld)
{
    __shared__ uint32_t sm[4 * TILE_U32];   // Ah | Al | Bh | Bl

    const int tid  = threadIdx.x;
    const int wid  = tid >> 5;
    const int lane = tid & 31;
    const int warpM = wid >> 2;
    const int warpN = wid & 3;
    const int bm = blockIdx.y * 128;
    const int bn = blockIdx.x * 128;
    const int nchunks = Kit >> 5;

    if (SPLIT) {
        const int bz = blockIdx.z;
        A += (size_t)bz * Kit;
        B += (size_t)bz * Kit;
        C += (size_t)bz * M * N;
    }

    const uint32_t smb = smem_u32(sm);

    float acc[16][4];
    #pragma unroll
    for (int i = 0; i < 16; i++)
        #pragma unroll
        for (int j = 0; j < 4; j++) acc[i][j] = 0.f;

    float4 ar[4], br[4];

    // ---- prologue ----
    #pragma unroll
    for (int i = 0; i < 4; i++) {
        int idx = i * 256 + tid;
        int row = idx >> 3, q = idx & 7;
        int gr = bm + row; if (gr >= M) gr = M - 1;
        ar[i] = *(const float4*)(A + (size_t)gr * ld + q * 4);
        br[i] = *(const float4*)(B + (size_t)(bn + row) * ld + q * 4);
    }
    #pragma unroll
    for (int i = 0; i < 4; i++) {
        int idx = i * 256 + tid;
        int row = idx >> 3, q = idx & 7;
        uint32_t h, l;
        split2(ar[i].x, ar[i].y, h, l);
        sm[row * ROWU + q * 2] = h;  sm[TILE_U32 + row * ROWU + q * 2] = l;
        split2(ar[i].z, ar[i].w, h, l);
        sm[row * ROWU + q * 2 + 1] = h;  sm[TILE_U32 + row * ROWU + q * 2 + 1] = l;
        split2(br[i].x, br[i].y, h, l);
        sm[2 * TILE_U32 + row * ROWU + q * 2] = h;
        sm[3 * TILE_U32 + row * ROWU + q * 2] = l;
        split2(br[i].z, br[i].w, h, l);
        sm[2 * TILE_U32 + row * ROWU + q * 2 + 1] = h;
        sm[3 * TILE_U32 + row * ROWU + q * 2 + 1] = l;
    }
    __syncthreads();

    const uint32_t aoff = (uint32_t)((lane & 15) * 80 + (lane >> 4) * 16);
    const uint32_t boff = (uint32_t)((((lane >> 4) & 1) * 8 + (lane & 7)) * 80 +
                                     ((lane >> 3) & 1) * 16);
    const uint32_t aBase = smb + (uint32_t)(warpM * 64) * 80 + aoff;
    const uint32_t bBase = smb + 2u * 10240u + (uint32_t)(warpN * 32) * 80 + boff;

    for (int c = 0; c < nchunks; c++) {
        const bool more = (c + 1 < nchunks);
        if (more) {
            const int k0 = (c + 1) * 32;
            #pragma unroll
            for (int i = 0; i < 4; i++) {
                int idx = i * 256 + tid;
                int row = idx >> 3, q = idx & 7;
                int gr = bm + row; if (gr >= M) gr = M - 1;
                ar[i] = *(const float4*)(A + (size_t)gr * ld + k0 + q * 4);
                br[i] = *(const float4*)(B + (size_t)(bn + row) * ld + k0 + q * 4);
            }
        }

        #pragma unroll
        for (int ks = 0; ks < 2; ks++) {
            const uint32_t kb = (uint32_t)(ks * 32);
            uint32_t ah[4][4], al[4][4], bh[2][4], bl[2][4];
            #pragma unroll
            for (int mt = 0; mt < 4; mt++)
                ldsm4(ah[mt], aBase + (uint32_t)(mt * 16) * 80 + kb);
            #pragma unroll
            for (int p = 0; p < 2; p++)
                ldsm4(bh[p], bBase + (uint32_t)(p * 16) * 80 + kb);
            #pragma unroll
            for (int mt = 0; mt < 4; mt++)
                #pragma unroll
                for (int nt = 0; nt < 4; nt++)
                    mma16816(acc[mt * 4 + nt], ah[mt], &bh[nt >> 1][(nt & 1) * 2]);
            #pragma unroll
            for (int p = 0; p < 2; p++)
                ldsm4(bl[p], bBase + 10240u + (uint32_t)(p * 16) * 80 + kb);
            #pragma unroll
            for (int mt = 0; mt < 4; mt++)
                #pragma unroll
                for (int nt = 0; nt < 4; nt++)
                    mma16816(acc[mt * 4 + nt], ah[mt], &bl[nt >> 1][(nt & 1) * 2]);
            #pragma unroll
            for (int mt = 0; mt < 4; mt++)
                ldsm4(al[mt], aBase + 10240u + (uint32_t)(mt * 16) * 80 + kb);
            #pragma unroll
            for (int mt = 0; mt < 4; mt++)
                #pragma unroll
                for (int nt = 0; nt < 4; nt++)
                    mma16816(acc[mt * 4 + nt], al[mt], &bh[nt >> 1][(nt & 1) * 2]);
        }
        __syncthreads();

        if (more) {
            #pragma unroll
            for (int i = 0; i < 4; i++) {
                int idx = i * 256 + tid;
                int row = idx >> 3, q = idx & 7;
                uint32_t h, l;
                split2(ar[i].x, ar[i].y, h, l);
                sm[row * ROWU + q * 2] = h;  sm[TILE_U32 + row * ROWU + q * 2] = l;
                split2(ar[i].z, ar[i].w, h, l);
                sm[row * ROWU + q * 2 + 1] = h;  sm[TILE_U32 + row * ROWU + q * 2 + 1] = l;
                split2(br[i].x, br[i].y, h, l);
                sm[2 * TILE_U32 + row * ROWU + q * 2] = h;
                sm[3 * TILE_U32 + row * ROWU + q * 2] = l;
                split2(br[i].z, br[i].w, h, l);
                sm[2 * TILE_U32 + row * ROWU + q * 2 + 1] = h;
                sm[3 * TILE_U32 + row * ROWU + q * 2 + 1] = l;
            }
            __syncthreads();
        }
    }

    const int gcol0 = bn + warpN * 32;
    #pragma unroll
    for (int mt = 0; mt < 4; mt++) {
        const int gr0 = bm + warpM * 64 + mt * 16 + (lane >> 2);
        #pragma unroll
        for (int nt = 0; nt < 4; nt++) {
            const int gc = gcol0 + nt * 8 + (lane & 3) * 2;
            float b0 = 0.f, b1 = 0.f;
            if (ADD_BIAS) { b0 = bias[gc]; b1 = bias[gc + 1]; }
            const float* cc = acc[mt * 4 + nt];
            if (gr0 < M) {
                C[(size_t)gr0 * N + gc]     = cc[0] + b0;
                C[(size_t)gr0 * N + gc + 1] = cc[1] + b1;
            }
            if (gr0 + 8 < M) {
                C[(size_t)(gr0 + 8) * N + gc]     = cc[2] + b0;
                C[(size_t)(gr0 + 8) * N + gc + 1] = cc[3] + b1;
            }
        }
    }
}

// split-K reduce: out[i] = sum_z part[z*MN + i]
__global__ __launch_bounds__(256) void reduce4(const float* __restrict__ part,
                                               float* __restrict__ out, int MN)
{
    int i = (blockIdx.x * 256 + threadIdx.x) * 4;
    if (i >= MN) return;
    float4 a = *(const float4*)(part + i);
    float4 b = *(const float4*)(part + MN + i);
    float4 c = *(const float4*)(part + 2 * MN + i);
    float4 d = *(const float4*)(part + 3 * MN + i);
    float4 r = make_float4(a.x + b.x + c.x + d.x, a.y + b.y + c.y + d.y,
                           a.z + b.z + c.z + d.z, a.w + b.w + c.w + d.w);
    *(float4*)(out + i) = r;
}

// ---------------------------------------------------------------------------
// LayerNorm over 512 columns, one block per row, in place.
// ---------------------------------------------------------------------------
__global__ __launch_bounds__(256) void ln_kernel(
    float* __restrict__ x, const float* __restrict__ g,
    const float* __restrict__ b)
{
    const int C = 512;
    float* row = x + (size_t)blockIdx.x * C;
    const int t = threadIdx.x;

    float v0 = row[t];
    float v1 = row[t + 256];
    float s  = v0 + v1;
    float sq = v0 * v0 + v1 * v1;

    #pragma unroll
    for (int o = 16; o > 0; o >>= 1) {
        s  += __shfl_xor_sync(0xffffffffu, s,  o);
        sq += __shfl_xor_sync(0xffffffffu, sq, o);
    }
    __shared__ float redS[8], redQ[8];
    const int warp = t >> 5, lane = t & 31;
    if (lane == 0) { redS[warp] = s; redQ[warp] = sq; }
    __syncthreads();
    float S = 0.f, Q = 0.f;
    #pragma unroll
    for (int w = 0; w < 8; w++) { S += redS[w]; Q += redQ[w]; }

    const float mu  = S * (1.0f / C);
    const float var = Q * (1.0f / C) - mu * mu;
    const float r   = rsqrtf(var + LN_EPS);

    row[t]       = (v0 - mu) * r * g[t]       + b[t];
    row[t + 256] = (v1 - mu) * r * g[t + 256] + b[t + 256];
}

// ---------------------------------------------------------------------------
// Flash attention, mma.sync bf16 hi/lo x3.
// Block: 64 queries x (head, batch). 128 threads = 4 warps; warp = 16 q rows.
// smem: K hi/lo + V hi/lo tiles [64 s][64 d] bf16, row stride 144B.
// Q A-fragments (scaled by 1/8) live in registers for the whole kernel.
// ---------------------------------------------------------------------------
#define QROWU 36   // u32 per smem row (64 bf16 data + pad) = 144B

__global__ __launch_bounds__(128) void attn_mma(
    const float* __restrict__ q, const float* __restrict__ kv,
    float* __restrict__ out, int S)
{
    __shared__ uint32_t sk[2][64 * QROWU];   // K hi/lo (Q hi/lo in prologue)
    __shared__ uint32_t sv[2][64 * QROWU];   // V hi/lo

    const int tid  = threadIdx.x;
    const int wid  = tid >> 5;
    const int lane = tid & 31;
    const int qb = blockIdx.x, h = blockIdx.y, b = blockIdx.z;

    const uint32_t skb0 = smem_u32(&sk[0][0]);
    const uint32_t skb1 = smem_u32(&sk[1][0]);
    const uint32_t svb0 = smem_u32(&sv[0][0]);
    const uint32_t svb1 = smem_u32(&sv[1][0]);

    // ---- stage Q (x 1/8) into sk, then ldmatrix into registers ----
    const float* qbase = q + ((size_t)(b * 1024 + qb * 64)) * 1024 + h * 64;
    #pragma unroll
    for (int it = 0; it < 8; it++) {
        int idx = it * 128 + tid;
        int row = idx >> 4, q4 = idx & 15;
        float4 v = *(const float4*)(qbase + (size_t)row * 1024 + q4 * 4);
        v.x *= 0.125f; v.y *= 0.125f; v.z *= 0.125f; v.w *= 0.125f;
        uint32_t hh, ll;
        split2(v.x, v.y, hh, ll);
        sk[0][row * QROWU + q4 * 2] = hh;  sk[1][row * QROWU + q4 * 2] = ll;
        split2(v.z, v.w, hh, ll);
        sk[0][row * QROWU + q4 * 2 + 1] = hh;  sk[1][row * QROWU + q4 * 2 + 1] = ll;
    }
    __syncthreads();

    uint32_t qh[4][4], ql[4][4];
    {
        const uint32_t aoff = (uint32_t)(wid * 16 + (lane & 15)) * 144u +
                              (uint32_t)(lane >> 4) * 16u;
        #pragma unroll
        for (int ks = 0; ks < 4; ks++) {
            ldsm4(qh[ks], skb0 + aoff + (uint32_t)ks * 32u);
            ldsm4(ql[ks], skb1 + aoff + (uint32_t)ks * 32u);
        }
    }
    __syncthreads();   // Q smem now free for K

    float acc[8][4];
    #pragma unroll
    for (int i = 0; i < 8; i++)
        #pragma unroll
        for (int j = 0; j < 4; j++) acc[i][j] = 0.f;
    float m0 = -1e30f, m1 = -1e30f, l0 = 0.f, l1 = 0.f;

    const float* kvb = kv + h * 128;
    const uint32_t boff = (uint32_t)(((lane >> 4) & 1) * 8 + (lane & 7)) * 144u +
                          (uint32_t)((lane >> 3) & 1) * 16u;

    for (int s0 = 0; s0 < S; s0 += 64) {
        // ---- stage K, V chunk ----
        #pragma unroll
        for (int it = 0; it < 8; it++) {
            int idx = it * 128 + tid;
            int row = idx >> 4, q4 = idx & 15;
            int s = s0 + row;
            float4 kvv = (s < S) ? *(const float4*)(kvb + (size_t)s * 2048 + q4 * 4)
                                 : make_float4(0.f, 0.f, 0.f, 0.f);
            float4 vvv = (s < S) ? *(const float4*)(kvb + (size_t)s * 2048 + 64 + q4 * 4)
                                 : make_float4(0.f, 0.f, 0.f, 0.f);
            uint32_t hh, ll;
            split2(kvv.x, kvv.y, hh, ll);
            sk[0][row * QROWU + q4 * 2] = hh;  sk[1][row * QROWU + q4 * 2] = ll;
            split2(kvv.z, kvv.w, hh, ll);
            sk[0][row * QROWU + q4 * 2 + 1] = hh;  sk[1][row * QROWU + q4 * 2 + 1] = ll;
            split2(vvv.x, vvv.y, hh, ll);
            sv[0][row * QROWU + q4 * 2] = hh;  sv[1][row * QROWU + q4 * 2] = ll;
            split2(vvv.z, vvv.w, hh, ll);
            sv[0][row * QROWU + q4 * 2 + 1] = hh;  sv[1][row * QROWU + q4 * 2 + 1] = ll;
        }
        __syncthreads();

        // ---- S = (Q/8) K^T : 3-term hi/lo ----
        float sf[8][4];
        #pragma unroll
        for (int i = 0; i < 8; i++)
            #pragma unroll
            for (int j = 0; j < 4; j++) sf[i][j] = 0.f;

        #pragma unroll
        for (int ks = 0; ks < 4; ks++) {
            const uint32_t kb = (uint32_t)ks * 32u;
            uint32_t kh[4][4], kl[4][4];
            #pragma unroll
            for (int p = 0; p < 4; p++) {
                ldsm4(kh[p], skb0 + boff + (uint32_t)(p * 16) * 144u + kb);
                ldsm4(kl[p], skb1 + boff + (uint32_t)(p * 16) * 144u + kb);
            }
            #pragma unroll
            for (int nt = 0; nt < 8; nt++) {
                mma16816(sf[nt], qh[ks], &kh[nt >> 1][(nt & 1) * 2]);
                mma16816(sf[nt], qh[ks], &kl[nt >> 1][(nt & 1) * 2]);
                mma16816(sf[nt], ql[ks], &kh[nt >> 1][(nt & 1) * 2]);
            }
        }

        // ---- mask tail ----
        if (s0 + 64 > S) {
            #pragma unroll
            for (int nt = 0; nt < 8; nt++) {
                int col = s0 + nt * 8 + (lane & 3) * 2;
                if (col >= S)     { sf[nt][0] = -1e30f; sf[nt][2] = -1e30f; }
                if (col + 1 >= S) { sf[nt][1] = -1e30f; sf[nt][3] = -1e30f; }
            }
        }

        // ---- online softmax (rows r0 = lane>>2, r1 = r0+8) ----
        float mx0 = -1e30f, mx1 = -1e30f;
        #pragma unroll
        for (int nt = 0; nt < 8; nt++) {
            mx0 = fmaxf(mx0, fmaxf(sf[nt][0], sf[nt][1]));
            mx1 = fmaxf(mx1, fmaxf(sf[nt][2], sf[nt][3]));
        }
        mx0 = fmaxf(mx0, __shfl_xor_sync(0xffffffffu, mx0, 1));
        mx0 = fmaxf(mx0, __shfl_xor_sync(0xffffffffu, mx0, 2));
        mx1 = fmaxf(mx1, __shfl_xor_sync(0xffffffffu, mx1, 1));
        mx1 = fmaxf(mx1, __shfl_xor_sync(0xffffffffu, mx1, 2));
        const float m0n = fmaxf(m0, mx0);
        const float m1n = fmaxf(m1, mx1);

        float sum0 = 0.f, sum1 = 0.f;
        #pragma unroll
        for (int nt = 0; nt < 8; nt++) {
            sf[nt][0] = __expf(sf[nt][0] - m0n);
            sf[nt][1] = __expf(sf[nt][1] - m0n);
            sf[nt][2] = __expf(sf[nt][2] - m1n);
            sf[nt][3] = __expf(sf[nt][3] - m1n);
            sum0 += sf[nt][0] + sf[nt][1];
            sum1 += sf[nt][2] + sf[nt][3];
        }
        sum0 += __shfl_xor_sync(0xffffffffu, sum0, 1);
        sum0 += __shfl_xor_sync(0xffffffffu, sum0, 2);
        sum1 += __shfl_xor_sync(0xffffffffu, sum1, 1);
        sum1 += __shfl_xor_sync(0xffffffffu, sum1, 2);

        const float c0 = __expf(m0 - m0n);
        const float c1 = __expf(m1 - m1n);
        l0 = l0 * c0 + sum0;  m0 = m0n;
        l1 = l1 * c1 + sum1;  m1 = m1n;
        #pragma unroll
        for (int dn = 0; dn < 8; dn++) {
            acc[dn][0] *= c0; acc[dn][1] *= c0;
            acc[dn][2] *= c1; acc[dn][3] *= c1;
        }

        // ---- acc += P V : 3-term hi/lo; P frags built from sf ----
        #pragma unroll
        for (int ks = 0; ks < 4; ks++) {
            uint32_t pah[4], pal[4];
            {
                const float* t0 = sf[2 * ks];
                const float* t1 = sf[2 * ks + 1];
                split2(t0[0], t0[1], pah[0], pal[0]);
                split2(t0[2], t0[3], pah[1], pal[1]);
                split2(t1[0], t1[1], pah[2], pal[2]);
                split2(t1[2], t1[3], pah[3], pal[3]);
            }
            const uint32_t vrow =
                (uint32_t)(ks * 16 + (lane & 7) + ((lane >> 3) & 1) * 8) * 144u;
            #pragma unroll
            for (int dp = 0; dp < 4; dp++) {
                uint32_t vh[4], vl[4];
                const uint32_t vo = vrow +
                    (uint32_t)(dp * 16 + ((lane >> 4) & 1) * 8) * 2u;
                ldsm4t(vh, svb0 + vo);
                ldsm4t(vl, svb1 + vo);
                mma16816(acc[2 * dp],     pah, &vh[0]);
                mma16816(acc[2 * dp + 1], pah, &vh[2]);
                mma16816(acc[2 * dp],     pah, &vl[0]);
                mma16816(acc[2 * dp + 1], pah, &vl[2]);
                mma16816(acc[2 * dp],     pal, &vh[0]);
                mma16816(acc[2 * dp + 1], pal, &vh[2]);
            }
        }
        __syncthreads();   // done reading K/V before next staging
    }

    // ---- epilogue ----
    const float inv0 = 1.0f / l0;
    const float inv1 = 1.0f / l1;
    const int r0 = qb * 64 + wid * 16 + (lane >> 2);
    float* ob = out + ((size_t)(b * 1024 + r0)) * 1024 + h * 64;
    #pragma unroll
    for (int nt = 0; nt < 8; nt++) {
        const int col = nt * 8 + (lane & 3) * 2;
        ob[col]     = acc[nt][0] * inv0;
        ob[col + 1] = acc[nt][1] * inv0;
        ob[(size_t)8 * 1024 + col]     = acc[nt][2] * inv1;
        ob[(size_t)8 * 1024 + col + 1] = acc[nt][3] * inv1;
    }
}

// ---------------------------------------------------------------------------
extern "C" void kernel_launch(void* const* d_in, const int* in_sizes, int n_in,
                              void* d_out, int out_size)
{
    (void)in_sizes; (void)n_in; (void)out_size;
    const float* te      = (const float*)d_in[0];
    const float* se      = (const float*)d_in[1];
    const float* q_a_w   = (const float*)d_in[3];
    const float* q_ln_g  = (const float*)d_in[4];
    const float* q_ln_b  = (const float*)d_in[5];
    const float* q_b_w   = (const float*)d_in[6];
    const float* kv_a_w  = (const float*)d_in[7];
    const float* kv_ln_g = (const float*)d_in[8];
    const float* kv_ln_b = (const float*)d_in[9];
    const float* kv_b_w  = (const float*)d_in[10];
    const float* out_w   = (const float*)d_in[11];
    const float* out_b   = (const float*)d_in[12];
    float* out = (float*)d_out;

    float *qa, *qbuf, *ckv, *kvb, *attn, *part;
    cudaGetSymbolAddress((void**)&qa,   g_qa);
    cudaGetSymbolAddress((void**)&qbuf, g_q);
    cudaGetSymbolAddress((void**)&ckv,  g_ckv);
    cudaGetSymbolAddress((void**)&kvb,  g_kv);
    cudaGetSymbolAddress((void**)&attn, g_attn);
    cudaGetSymbolAddress((void**)&part, g_part);

    // q path: (4096x512 K=1024), LN, (4096x1024 K=512)
    gemm_mma<false, false><<<dim3(4, 32), 256>>>(te, q_a_w, nullptr, qa,
                                                 4096, 512, 1024, 1024);
    ln_kernel<<<4096, 256>>>(qa, q_ln_g, q_ln_b);
    gemm_mma<false, false><<<dim3(8, 32), 256>>>(qa, q_b_w, nullptr, qbuf,
                                                 4096, 1024, 512, 512);

    // kv path: (1000x512 K=4096 split-K x4), LN, (1000x2048 K=512)
    gemm_mma<false, true><<<dim3(4, 8, 4), 256>>>(se, kv_a_w, nullptr, part,
                                                  1000, 512, 1024, 4096);
    reduce4<<<500, 256>>>(part, ckv, 1000 * 512);
    ln_kernel<<<1000, 256>>>(ckv, kv_ln_g, kv_ln_b);
    gemm_mma<false, false><<<dim3(16, 8), 256>>>(ckv, kv_b_w, nullptr, kvb,
                                                 1000, 2048, 512, 512);

    // attention (tensor-core flash)
    attn_mma<<<dim3(16, 16, 4), 128>>>(qbuf, kvb, attn, 1000);

    // output projection + bias: (4096x4096 K=1024)
    gemm_mma<true, false><<<dim3(32, 32), 256>>>(attn, out_w, out_b, out,
                                                 4096, 4096, 1024, 1024);
}

// round 9
// speedup vs baseline: 3.6942x; 1.2209x over previous
#include <cuda_runtime.h>
#include <cstdint>

// ===========================================================================
// ReprogrammingLayer_MLA — round 9
//   GEMMs: mma.sync m16n8k16 bf16 hi/lo x3, now DOUBLE-BUFFERED smem
//          (one __syncthreads per K-chunk; LDG/convert/STS overlap MMA)
//   Attention: flash mma.sync bf16 hi/lo x3 (proven round 8)
//   LayerNorm: fp32 SIMT
// ===========================================================================

#define LN_EPS 1e-5f

// scratch (device globals; no allocation allowed)
__device__ float g_qa  [4096u * 512u];
__device__ float g_q   [4096u * 1024u];
__device__ float g_ckv [1000u * 512u];
__device__ float g_kv  [1000u * 2048u];
__device__ float g_attn[4096u * 1024u];
__device__ float g_part[4u * 1000u * 512u];   // split-K partials

// ---------------------------------------------------------------------------
// helpers
// ---------------------------------------------------------------------------
__device__ __forceinline__ uint32_t smem_u32(const void* p) {
    uint32_t a;
    asm("{ .reg .u64 t; cvta.to.shared.u64 t, %1; cvt.u32.u64 %0, t; }"
        : "=r"(a) : "l"(p));
    return a;
}

__device__ __forceinline__ uint32_t pack_bf16(float lo, float hi) {
    uint32_t r;
    asm("cvt.rn.bf16x2.f32 %0, %1, %2;" : "=r"(r) : "f"(hi), "f"(lo));
    return r;
}

__device__ __forceinline__ void ldsm4(uint32_t* r, uint32_t addr) {
    asm volatile("ldmatrix.sync.aligned.m8n8.x4.shared.b16 {%0,%1,%2,%3}, [%4];"
                 : "=r"(r[0]), "=r"(r[1]), "=r"(r[2]), "=r"(r[3]) : "r"(addr));
}
__device__ __forceinline__ void ldsm4t(uint32_t* r, uint32_t addr) {
    asm volatile("ldmatrix.sync.aligned.m8n8.x4.trans.shared.b16 {%0,%1,%2,%3}, [%4];"
                 : "=r"(r[0]), "=r"(r[1]), "=r"(r[2]), "=r"(r[3]) : "r"(addr));
}

__device__ __forceinline__ void mma16816(float* c, const uint32_t* a,
                                         const uint32_t* b) {
    asm volatile(
        "mma.sync.aligned.m16n8k16.row.col.f32.bf16.bf16.f32 "
        "{%0,%1,%2,%3}, {%4,%5,%6,%7}, {%8,%9}, {%0,%1,%2,%3};"
        : "+f"(c[0]), "+f"(c[1]), "+f"(c[2]), "+f"(c[3])
        : "r"(a[0]), "r"(a[1]), "r"(a[2]), "r"(a[3]), "r"(b[0]), "r"(b[1]));
}

__device__ __forceinline__ void split2(float x, float y, uint32_t& h, uint32_t& l) {
    h = pack_bf16(x, y);
    float hx = __uint_as_float(h << 16);
    float hy = __uint_as_float(h & 0xffff0000u);
    l = pack_bf16(x - hx, y - hy);
}

// ---------------------------------------------------------------------------
// bf16x3 mma.sync GEMM, double-buffered smem.
// BM=BN=128, BK=32; per buffer: Ah|Al|Bh|Bl tiles, row stride 80B = 40960 B.
// ---------------------------------------------------------------------------
#define ROWU 20
#define TILE_U32 (128 * ROWU)
#define BUF_U32  (4 * TILE_U32)      // 10240 u32 = 40960 B
#define GEMM_DSMEM (2 * BUF_U32 * 4) // 81920 B

template<bool ADD_BIAS, bool SPLIT>
__global__ __launch_bounds__(256) void gemm_mma(
    const float* __restrict__ A, const float* __restrict__ B,
    const float* __restrict__ bias, float* __restrict__ C,
    int M, int N, int Kit, int ld)
{
    extern __shared__ uint32_t sm[];     // [2][Ah|Al|Bh|Bl]

    const int tid  = threadIdx.x;
    const int wid  = tid >> 5;
    const int lane = tid & 31;
    const int warpM = wid >> 2;
    const int warpN = wid & 3;
    const int bm = blockIdx.y * 128;
    const int bn = blockIdx.x * 128;
    const int nchunks = Kit >> 5;

    if (SPLIT) {
        const int bz = blockIdx.z;
        A += (size_t)bz * Kit;
        B += (size_t)bz * Kit;
        C += (size_t)bz * M * N;
    }

    const uint32_t smb = smem_u32(sm);

    float acc[16][4];
    #pragma unroll
    for (int i = 0; i < 16; i++)
        #pragma unroll
        for (int j = 0; j < 4; j++) acc[i][j] = 0.f;

    float4 ar[4], br[4];

    // ---- prologue: stage chunk 0 into buffer 0 ----
    #pragma unroll
    for (int i = 0; i < 4; i++) {
        int idx = i * 256 + tid;
        int row = idx >> 3, q = idx & 7;
        int gr = bm + row; if (gr >= M) gr = M - 1;
        ar[i] = *(const float4*)(A + (size_t)gr * ld + q * 4);
        br[i] = *(const float4*)(B + (size_t)(bn + row) * ld + q * 4);
    }
    #pragma unroll
    for (int i = 0; i < 4; i++) {
        int idx = i * 256 + tid;
        int row = idx >> 3, q = idx & 7;
        uint32_t h, l;
        split2(ar[i].x, ar[i].y, h, l);
        sm[row * ROWU + q * 2] = h;  sm[TILE_U32 + row * ROWU + q * 2] = l;
        split2(ar[i].z, ar[i].w, h, l);
        sm[row * ROWU + q * 2 + 1] = h;  sm[TILE_U32 + row * ROWU + q * 2 + 1] = l;
        split2(br[i].x, br[i].y, h, l);
        sm[2 * TILE_U32 + row * ROWU + q * 2] = h;
        sm[3 * TILE_U32 + row * ROWU + q * 2] = l;
        split2(br[i].z, br[i].w, h, l);
        sm[2 * TILE_U32 + row * ROWU + q * 2 + 1] = h;
        sm[3 * TILE_U32 + row * ROWU + q * 2 + 1] = l;
    }
    __syncthreads();

    const uint32_t aoff = (uint32_t)((lane & 15) * 80 + (lane >> 4) * 16);
    const uint32_t boff = (uint32_t)((((lane >> 4) & 1) * 8 + (lane & 7)) * 80 +
                                     ((lane >> 3) & 1) * 16);
    const uint32_t aBase0 = smb + (uint32_t)(warpM * 64) * 80 + aoff;
    const uint32_t bBase0 = smb + 2u * 10240u + (uint32_t)(warpN * 32) * 80 + boff;

    for (int c = 0; c < nchunks; c++) {
        const bool more = (c + 1 < nchunks);
        const uint32_t cbuf = (uint32_t)(c & 1) * 40960u;
        const uint32_t nbuf = (uint32_t)((c + 1) & 1) * BUF_U32;  // u32 index

        // issue next-chunk loads first (hidden behind MMA below)
        if (more) {
            const int k0 = (c + 1) * 32;
            #pragma unroll
            for (int i = 0; i < 4; i++) {
                int idx = i * 256 + tid;
                int row = idx >> 3, q = idx & 7;
                int gr = bm + row; if (gr >= M) gr = M - 1;
                ar[i] = *(const float4*)(A + (size_t)gr * ld + k0 + q * 4);
                br[i] = *(const float4*)(B + (size_t)(bn + row) * ld + k0 + q * 4);
            }
        }

        // ---- compute on buffer c&1 ----
        const uint32_t aBase = aBase0 + cbuf;
        const uint32_t bBase = bBase0 + cbuf;
        #pragma unroll
        for (int ks = 0; ks < 2; ks++) {
            const uint32_t kb = (uint32_t)(ks * 32);
            uint32_t ah[4][4], al[4][4], bh[2][4], bl[2][4];
            #pragma unroll
            for (int mt = 0; mt < 4; mt++)
                ldsm4(ah[mt], aBase + (uint32_t)(mt * 16) * 80 + kb);
            #pragma unroll
            for (int p = 0; p < 2; p++)
                ldsm4(bh[p], bBase + (uint32_t)(p * 16) * 80 + kb);
            #pragma unroll
            for (int mt = 0; mt < 4; mt++)
                #pragma unroll
                for (int nt = 0; nt < 4; nt++)
                    mma16816(acc[mt * 4 + nt], ah[mt], &bh[nt >> 1][(nt & 1) * 2]);
            #pragma unroll
            for (int p = 0; p < 2; p++)
                ldsm4(bl[p], bBase + 10240u + (uint32_t)(p * 16) * 80 + kb);
            #pragma unroll
            for (int mt = 0; mt < 4; mt++)
                #pragma unroll
                for (int nt = 0; nt < 4; nt++)
                    mma16816(acc[mt * 4 + nt], ah[mt], &bl[nt >> 1][(nt & 1) * 2]);
            #pragma unroll
            for (int mt = 0; mt < 4; mt++)
                ldsm4(al[mt], aBase + 10240u + (uint32_t)(mt * 16) * 80 + kb);
            #pragma unroll
            for (int mt = 0; mt < 4; mt++)
                #pragma unroll
                for (int nt = 0; nt < 4; nt++)
                    mma16816(acc[mt * 4 + nt], al[mt], &bh[nt >> 1][(nt & 1) * 2]);
        }

        // ---- store next chunk into the other buffer ----
        if (more) {
            uint32_t* smn = sm + nbuf;
            #pragma unroll
            for (int i = 0; i < 4; i++) {
                int idx = i * 256 + tid;
                int row = idx >> 3, q = idx & 7;
                uint32_t h, l;
                split2(ar[i].x, ar[i].y, h, l);
                smn[row * ROWU + q * 2] = h;  smn[TILE_U32 + row * ROWU + q * 2] = l;
                split2(ar[i].z, ar[i].w, h, l);
                smn[row * ROWU + q * 2 + 1] = h;
                smn[TILE_U32 + row * ROWU + q * 2 + 1] = l;
                split2(br[i].x, br[i].y, h, l);
                smn[2 * TILE_U32 + row * ROWU + q * 2] = h;
                smn[3 * TILE_U32 + row * ROWU + q * 2] = l;
                split2(br[i].z, br[i].w, h, l);
                smn[2 * TILE_U32 + row * ROWU + q * 2 + 1] = h;
                smn[3 * TILE_U32 + row * ROWU + q * 2 + 1] = l;
            }
        }
        __syncthreads();
    }

    const int gcol0 = bn + warpN * 32;
    #pragma unroll
    for (int mt = 0; mt < 4; mt++) {
        const int gr0 = bm + warpM * 64 + mt * 16 + (lane >> 2);
        #pragma unroll
        for (int nt = 0; nt < 4; nt++) {
            const int gc = gcol0 + nt * 8 + (lane & 3) * 2;
            float b0 = 0.f, b1 = 0.f;
            if (ADD_BIAS) { b0 = bias[gc]; b1 = bias[gc + 1]; }
            const float* cc = acc[mt * 4 + nt];
            if (gr0 < M) {
                C[(size_t)gr0 * N + gc]     = cc[0] + b0;
                C[(size_t)gr0 * N + gc + 1] = cc[1] + b1;
            }
            if (gr0 + 8 < M) {
                C[(size_t)(gr0 + 8) * N + gc]     = cc[2] + b0;
                C[(size_t)(gr0 + 8) * N + gc + 1] = cc[3] + b1;
            }
        }
    }
}

// split-K reduce
__global__ __launch_bounds__(256) void reduce4(const float* __restrict__ part,
                                               float* __restrict__ out, int MN)
{
    int i = (blockIdx.x * 256 + threadIdx.x) * 4;
    if (i >= MN) return;
    float4 a = *(const float4*)(part + i);
    float4 b = *(const float4*)(part + MN + i);
    float4 c = *(const float4*)(part + 2 * MN + i);
    float4 d = *(const float4*)(part + 3 * MN + i);
    *(float4*)(out + i) = make_float4(a.x + b.x + c.x + d.x, a.y + b.y + c.y + d.y,
                                      a.z + b.z + c.z + d.z, a.w + b.w + c.w + d.w);
}

// ---------------------------------------------------------------------------
// LayerNorm over 512 columns, one block per row, in place.
// ---------------------------------------------------------------------------
__global__ __launch_bounds__(256) void ln_kernel(
    float* __restrict__ x, const float* __restrict__ g,
    const float* __restrict__ b)
{
    const int C = 512;
    float* row = x + (size_t)blockIdx.x * C;
    const int t = threadIdx.x;

    float v0 = row[t];
    float v1 = row[t + 256];
    float s  = v0 + v1;
    float sq = v0 * v0 + v1 * v1;

    #pragma unroll
    for (int o = 16; o > 0; o >>= 1) {
        s  += __shfl_xor_sync(0xffffffffu, s,  o);
        sq += __shfl_xor_sync(0xffffffffu, sq, o);
    }
    __shared__ float redS[8], redQ[8];
    const int warp = t >> 5, lane = t & 31;
    if (lane == 0) { redS[warp] = s; redQ[warp] = sq; }
    __syncthreads();
    float S = 0.f, Q = 0.f;
    #pragma unroll
    for (int w = 0; w < 8; w++) { S += redS[w]; Q += redQ[w]; }

    const float mu  = S * (1.0f / C);
    const float var = Q * (1.0f / C) - mu * mu;
    const float r   = rsqrtf(var + LN_EPS);

    row[t]       = (v0 - mu) * r * g[t]       + b[t];
    row[t + 256] = (v1 - mu) * r * g[t + 256] + b[t + 256];
}

// ---------------------------------------------------------------------------
// Flash attention, mma.sync bf16 hi/lo x3 (round 8, unchanged)
// ---------------------------------------------------------------------------
#define QROWU 36

__global__ __launch_bounds__(128) void attn_mma(
    const float* __restrict__ q, const float* __restrict__ kv,
    float* __restrict__ out, int S)
{
    __shared__ uint32_t sk[2][64 * QROWU];
    __shared__ uint32_t sv[2][64 * QROWU];

    const int tid  = threadIdx.x;
    const int wid  = tid >> 5;
    const int lane = tid & 31;
    const int qb = blockIdx.x, h = blockIdx.y, b = blockIdx.z;

    const uint32_t skb0 = smem_u32(&sk[0][0]);
    const uint32_t skb1 = smem_u32(&sk[1][0]);
    const uint32_t svb0 = smem_u32(&sv[0][0]);
    const uint32_t svb1 = smem_u32(&sv[1][0]);

    const float* qbase = q + ((size_t)(b * 1024 + qb * 64)) * 1024 + h * 64;
    #pragma unroll
    for (int it = 0; it < 8; it++) {
        int idx = it * 128 + tid;
        int row = idx >> 4, q4 = idx & 15;
        float4 v = *(const float4*)(qbase + (size_t)row * 1024 + q4 * 4);
        v.x *= 0.125f; v.y *= 0.125f; v.z *= 0.125f; v.w *= 0.125f;
        uint32_t hh, ll;
        split2(v.x, v.y, hh, ll);
        sk[0][row * QROWU + q4 * 2] = hh;  sk[1][row * QROWU + q4 * 2] = ll;
        split2(v.z, v.w, hh, ll);
        sk[0][row * QROWU + q4 * 2 + 1] = hh;  sk[1][row * QROWU + q4 * 2 + 1] = ll;
    }
    __syncthreads();

    uint32_t qh[4][4], ql[4][4];
    {
        const uint32_t aoff = (uint32_t)(wid * 16 + (lane & 15)) * 144u +
                              (uint32_t)(lane >> 4) * 16u;
        #pragma unroll
        for (int ks = 0; ks < 4; ks++) {
            ldsm4(qh[ks], skb0 + aoff + (uint32_t)ks * 32u);
            ldsm4(ql[ks], skb1 + aoff + (uint32_t)ks * 32u);
        }
    }
    __syncthreads();

    float acc[8][4];
    #pragma unroll
    for (int i = 0; i < 8; i++)
        #pragma unroll
        for (int j = 0; j < 4; j++) acc[i][j] = 0.f;
    float m0 = -1e30f, m1 = -1e30f, l0 = 0.f, l1 = 0.f;

    const float* kvb = kv + h * 128;
    const uint32_t boff = (uint32_t)(((lane >> 4) & 1) * 8 + (lane & 7)) * 144u +
                          (uint32_t)((lane >> 3) & 1) * 16u;

    for (int s0 = 0; s0 < S; s0 += 64) {
        #pragma unroll
        for (int it = 0; it < 8; it++) {
            int idx = it * 128 + tid;
            int row = idx >> 4, q4 = idx & 15;
            int s = s0 + row;
            float4 kvv = (s < S) ? *(const float4*)(kvb + (size_t)s * 2048 + q4 * 4)
                                 : make_float4(0.f, 0.f, 0.f, 0.f);
            float4 vvv = (s < S) ? *(const float4*)(kvb + (size_t)s * 2048 + 64 + q4 * 4)
                                 : make_float4(0.f, 0.f, 0.f, 0.f);
            uint32_t hh, ll;
            split2(kvv.x, kvv.y, hh, ll);
            sk[0][row * QROWU + q4 * 2] = hh;  sk[1][row * QROWU + q4 * 2] = ll;
            split2(kvv.z, kvv.w, hh, ll);
            sk[0][row * QROWU + q4 * 2 + 1] = hh;  sk[1][row * QROWU + q4 * 2 + 1] = ll;
            split2(vvv.x, vvv.y, hh, ll);
            sv[0][row * QROWU + q4 * 2] = hh;  sv[1][row * QROWU + q4 * 2] = ll;
            split2(vvv.z, vvv.w, hh, ll);
            sv[0][row * QROWU + q4 * 2 + 1] = hh;  sv[1][row * QROWU + q4 * 2 + 1] = ll;
        }
        __syncthreads();

        float sf[8][4];
        #pragma unroll
        for (int i = 0; i < 8; i++)
            #pragma unroll
            for (int j = 0; j < 4; j++) sf[i][j] = 0.f;

        #pragma unroll
        for (int ks = 0; ks < 4; ks++) {
            const uint32_t kb = (uint32_t)ks * 32u;
            uint32_t kh[4][4], kl[4][4];
            #pragma unroll
            for (int p = 0; p < 4; p++) {
                ldsm4(kh[p], skb0 + boff + (uint32_t)(p * 16) * 144u + kb);
                ldsm4(kl[p], skb1 + boff + (uint32_t)(p * 16) * 144u + kb);
            }
            #pragma unroll
            for (int nt = 0; nt < 8; nt++) {
                mma16816(sf[nt], qh[ks], &kh[nt >> 1][(nt & 1) * 2]);
                mma16816(sf[nt], qh[ks], &kl[nt >> 1][(nt & 1) * 2]);
                mma16816(sf[nt], ql[ks], &kh[nt >> 1][(nt & 1) * 2]);
            }
        }

        if (s0 + 64 > S) {
            #pragma unroll
            for (int nt = 0; nt < 8; nt++) {
                int col = s0 + nt * 8 + (lane & 3) * 2;
                if (col >= S)     { sf[nt][0] = -1e30f; sf[nt][2] = -1e30f; }
                if (col + 1 >= S) { sf[nt][1] = -1e30f; sf[nt][3] = -1e30f; }
            }
        }

        float mx0 = -1e30f, mx1 = -1e30f;
        #pragma unroll
        for (int nt = 0; nt < 8; nt++) {
            mx0 = fmaxf(mx0, fmaxf(sf[nt][0], sf[nt][1]));
            mx1 = fmaxf(mx1, fmaxf(sf[nt][2], sf[nt][3]));
        }
        mx0 = fmaxf(mx0, __shfl_xor_sync(0xffffffffu, mx0, 1));
        mx0 = fmaxf(mx0, __shfl_xor_sync(0xffffffffu, mx0, 2));
        mx1 = fmaxf(mx1, __shfl_xor_sync(0xffffffffu, mx1, 1));
        mx1 = fmaxf(mx1, __shfl_xor_sync(0xffffffffu, mx1, 2));
        const float m0n = fmaxf(m0, mx0);
        const float m1n = fmaxf(m1, mx1);

        float sum0 = 0.f, sum1 = 0.f;
        #pragma unroll
        for (int nt = 0; nt < 8; nt++) {
            sf[nt][0] = __expf(sf[nt][0] - m0n);
            sf[nt][1] = __expf(sf[nt][1] - m0n);
            sf[nt][2] = __expf(sf[nt][2] - m1n);
            sf[nt][3] = __expf(sf[nt][3] - m1n);
            sum0 += sf[nt][0] + sf[nt][1];
            sum1 += sf[nt][2] + sf[nt][3];
        }
        sum0 += __shfl_xor_sync(0xffffffffu, sum0, 1);
        sum0 += __shfl_xor_sync(0xffffffffu, sum0, 2);
        sum1 += __shfl_xor_sync(0xffffffffu, sum1, 1);
        sum1 += __shfl_xor_sync(0xffffffffu, sum1, 2);

        const float c0 = __expf(m0 - m0n);
        const float c1 = __expf(m1 - m1n);
        l0 = l0 * c0 + sum0;  m0 = m0n;
        l1 = l1 * c1 + sum1;  m1 = m1n;
        #pragma unroll
        for (int dn = 0; dn < 8; dn++) {
            acc[dn][0] *= c0; acc[dn][1] *= c0;
            acc[dn][2] *= c1; acc[dn][3] *= c1;
        }

        #pragma unroll
        for (int ks = 0; ks < 4; ks++) {
            uint32_t pah[4], pal[4];
            {
                const float* t0 = sf[2 * ks];
                const float* t1 = sf[2 * ks + 1];
                split2(t0[0], t0[1], pah[0], pal[0]);
                split2(t0[2], t0[3], pah[1], pal[1]);
                split2(t1[0], t1[1], pah[2], pal[2]);
                split2(t1[2], t1[3], pah[3], pal[3]);
            }
            const uint32_t vrow =
                (uint32_t)(ks * 16 + (lane & 7) + ((lane >> 3) & 1) * 8) * 144u;
            #pragma unroll
            for (int dp = 0; dp < 4; dp++) {
                uint32_t vh[4], vl[4];
                const uint32_t vo = vrow +
                    (uint32_t)(dp * 16 + ((lane >> 4) & 1) * 8) * 2u;
                ldsm4t(vh, svb0 + vo);
                ldsm4t(vl, svb1 + vo);
                mma16816(acc[2 * dp],     pah, &vh[0]);
                mma16816(acc[2 * dp + 1], pah, &vh[2]);
                mma16816(acc[2 * dp],     pah, &vl[0]);
                mma16816(acc[2 * dp + 1], pah, &vl[2]);
                mma16816(acc[2 * dp],     pal, &vh[0]);
                mma16816(acc[2 * dp + 1], pal, &vh[2]);
            }
        }
        __syncthreads();
    }

    const float inv0 = 1.0f / l0;
    const float inv1 = 1.0f / l1;
    const int r0 = qb * 64 + wid * 16 + (lane >> 2);
    float* ob = out + ((size_t)(b * 1024 + r0)) * 1024 + h * 64;
    #pragma unroll
    for (int nt = 0; nt < 8; nt++) {
        const int col = nt * 8 + (lane & 3) * 2;
        ob[col]     = acc[nt][0] * inv0;
        ob[col + 1] = acc[nt][1] * inv0;
        ob[(size_t)8 * 1024 + col]     = acc[nt][2] * inv1;
        ob[(size_t)8 * 1024 + col + 1] = acc[nt][3] * inv1;
    }
}

// ---------------------------------------------------------------------------
extern "C" void kernel_launch(void* const* d_in, const int* in_sizes, int n_in,
                              void* d_out, int out_size)
{
    (void)in_sizes; (void)n_in; (void)out_size;
    const float* te      = (const float*)d_in[0];
    const float* se      = (const float*)d_in[1];
    const float* q_a_w   = (const float*)d_in[3];
    const float* q_ln_g  = (const float*)d_in[4];
    const float* q_ln_b  = (const float*)d_in[5];
    const float* q_b_w   = (const float*)d_in[6];
    const float* kv_a_w  = (const float*)d_in[7];
    const float* kv_ln_g = (const float*)d_in[8];
    const float* kv_ln_b = (const float*)d_in[9];
    const float* kv_b_w  = (const float*)d_in[10];
    const float* out_w   = (const float*)d_in[11];
    const float* out_b   = (const float*)d_in[12];
    float* out = (float*)d_out;

    float *qa, *qbuf, *ckv, *kvb, *attn, *part;
    cudaGetSymbolAddress((void**)&qa,   g_qa);
    cudaGetSymbolAddress((void**)&qbuf, g_q);
    cudaGetSymbolAddress((void**)&ckv,  g_ckv);
    cudaGetSymbolAddress((void**)&kvb,  g_kv);
    cudaGetSymbolAddress((void**)&attn, g_attn);
    cudaGetSymbolAddress((void**)&part, g_part);

    cudaFuncSetAttribute(gemm_mma<false, false>,
                         cudaFuncAttributeMaxDynamicSharedMemorySize, GEMM_DSMEM);
    cudaFuncSetAttribute(gemm_mma<false, true>,
                         cudaFuncAttributeMaxDynamicSharedMemorySize, GEMM_DSMEM);
    cudaFuncSetAttribute(gemm_mma<true, false>,
                         cudaFuncAttributeMaxDynamicSharedMemorySize, GEMM_DSMEM);

    // q path
    gemm_mma<false, false><<<dim3(4, 32), 256, GEMM_DSMEM>>>(
        te, q_a_w, nullptr, qa, 4096, 512, 1024, 1024);
    ln_kernel<<<4096, 256>>>(qa, q_ln_g, q_ln_b);
    gemm_mma<false, false><<<dim3(8, 32), 256, GEMM_DSMEM>>>(
        qa, q_b_w, nullptr, qbuf, 4096, 1024, 512, 512);

    // kv path (split-K x4 on kv_a)
    gemm_mma<false, true><<<dim3(4, 8, 4), 256, GEMM_DSMEM>>>(
        se, kv_a_w, nullptr, part, 1000, 512, 1024, 4096);
    reduce4<<<500, 256>>>(part, ckv, 1000 * 512);
    ln_kernel<<<1000, 256>>>(ckv, kv_ln_g, kv_ln_b);
    gemm_mma<false, false><<<dim3(16, 8), 256, GEMM_DSMEM>>>(
        ckv, kv_b_w, nullptr, kvb, 1000, 2048, 512, 512);

    // attention
    attn_mma<<<dim3(16, 16, 4), 128>>>(qbuf, kvb, attn, 1000);

    // output projection + bias
    gemm_mma<true, false><<<dim3(32, 32), 256, GEMM_DSMEM>>>(
        attn, out_w, out_b, out, 4096, 4096, 1024, 1024);
}